// round 6
// baseline (speedup 1.0000x reference)
#include <cuda_runtime.h>
#include <cuda_fp16.h>

#define NN   50000
#define NE   1250000
#define HID  64
#define NL   3
#define NG   64
#define EPSV 1e-5f

#define SCAN_BS   256
#define SCAN_NBLK ((NN + SCAN_BS - 1) / SCAN_BS)   // 196

// -------- device scratch (no runtime allocation allowed) --------
__device__ unsigned int d_hhA[NN * 32];   // half2 node features (128B/row)
__device__ unsigned int d_hhB[NN * 32];
__device__ int2  d_epk[NE];      // packed (src, weight-bits) grouped by dst
__device__ int   d_deg[NN];
__device__ int   d_ptr[NN + 1];
__device__ int   d_cur[NN];
__device__ int   d_bsum[SCAN_NBLK];
__device__ int   d_boff[SCAN_NBLK];
__device__ float d_psum[NG * HID];
__device__ int   d_pmax[NG * HID];   // float bits; post-ReLU values >= 0
__device__ int   d_pcnt[NG];

// -------- zero the per-launch scratch --------
__global__ void zero_kernel() {
    int i = blockIdx.x * blockDim.x + threadIdx.x;
    int stride = gridDim.x * blockDim.x;
    for (int k = i; k < NN; k += stride) d_deg[k] = 0;
    for (int k = i; k < NG * HID; k += stride) { d_psum[k] = 0.f; d_pmax[k] = 0; }
    if (i < NG) d_pcnt[i] = 0;
}

// -------- convert emb (fp32) -> half2 table --------
__global__ void convert_kernel(const float* __restrict__ emb) {
    int i = blockIdx.x * blockDim.x + threadIdx.x;
    if (i < NN * 32) {
        float2 v = ((const float2*)emb)[i];
        __half2 h = __floats2half2_rn(v.x, v.y);
        d_hhA[i] = *(unsigned int*)&h;
    }
}

// -------- CSR build: count degrees of dst (4-way MLP) --------
__global__ void count_kernel(const int* __restrict__ dst, int ne, int T) {
    int t = blockIdx.x * blockDim.x + threadIdx.x;
    if (t >= T) return;
    int e0 = t, e1 = t + T, e2 = t + 2 * T, e3 = t + 3 * T;
    int d0 = (e0 < ne) ? dst[e0] : -1;
    int d1 = (e1 < ne) ? dst[e1] : -1;
    int d2 = (e2 < ne) ? dst[e2] : -1;
    int d3 = (e3 < ne) ? dst[e3] : -1;
    if (d0 >= 0) atomicAdd(&d_deg[d0], 1);
    if (d1 >= 0) atomicAdd(&d_deg[d1], 1);
    if (d2 >= 0) atomicAdd(&d_deg[d2], 1);
    if (d3 >= 0) atomicAdd(&d_deg[d3], 1);
}

// -------- 3-phase parallel scan --------
__global__ void scan_phase1(int n) {
    __shared__ int sm[SCAN_BS];
    int t = threadIdx.x;
    int idx = blockIdx.x * SCAN_BS + t;
    sm[t] = (idx < n) ? d_deg[idx] : 0;
    __syncthreads();
#pragma unroll
    for (int off = SCAN_BS / 2; off > 0; off >>= 1) {
        if (t < off) sm[t] += sm[t + off];
        __syncthreads();
    }
    if (t == 0) d_bsum[blockIdx.x] = sm[0];
}

__global__ void scan_phase2() {
    __shared__ int sm[SCAN_NBLK];
    int t = threadIdx.x;
    if (t < SCAN_NBLK) sm[t] = d_bsum[t];
    __syncthreads();
    for (int off = 1; off < SCAN_NBLK; off <<= 1) {
        int v = (t < SCAN_NBLK && t >= off) ? sm[t - off] : 0;
        __syncthreads();
        if (t < SCAN_NBLK) sm[t] += v;
        __syncthreads();
    }
    if (t < SCAN_NBLK) d_boff[t] = (t == 0) ? 0 : sm[t - 1];
    if (t == 0) d_ptr[NN] = sm[SCAN_NBLK - 1];
}

__global__ void scan_phase3(int n) {
    __shared__ int sm[SCAN_BS];
    int t = threadIdx.x;
    int idx = blockIdx.x * SCAN_BS + t;
    int v = (idx < n) ? d_deg[idx] : 0;
    sm[t] = v;
    __syncthreads();
#pragma unroll
    for (int off = 1; off < SCAN_BS; off <<= 1) {
        int u = (t >= off) ? sm[t - off] : 0;
        __syncthreads();
        sm[t] += u;
        __syncthreads();
    }
    if (idx < n) {
        int p = d_boff[blockIdx.x] + sm[t] - v;   // exclusive
        d_ptr[idx] = p;
        d_cur[idx] = p;
    }
}

// -------- CSR build: scatter packed (src, w) grouped by dst (4-way MLP) ----
__global__ void scatter_kernel(const int* __restrict__ src, const int* __restrict__ dst,
                               const float* __restrict__ w, int ne, int T) {
    int t = blockIdx.x * blockDim.x + threadIdx.x;
    if (t >= T) return;
    int e0 = t, e1 = t + T, e2 = t + 2 * T, e3 = t + 3 * T;
    int d0 = (e0 < ne) ? dst[e0] : -1;
    int d1 = (e1 < ne) ? dst[e1] : -1;
    int d2 = (e2 < ne) ? dst[e2] : -1;
    int d3 = (e3 < ne) ? dst[e3] : -1;
    int s0 = (e0 < ne) ? src[e0] : 0;
    int s1 = (e1 < ne) ? src[e1] : 0;
    int s2 = (e2 < ne) ? src[e2] : 0;
    int s3 = (e3 < ne) ? src[e3] : 0;
    float w0 = (e0 < ne) ? w[e0] : 0.f;
    float w1 = (e1 < ne) ? w[e1] : 0.f;
    float w2 = (e2 < ne) ? w[e2] : 0.f;
    float w3 = (e3 < ne) ? w[e3] : 0.f;
    if (d0 >= 0) { int p = atomicAdd(&d_cur[d0], 1); d_epk[p] = make_int2(s0, __float_as_int(w0)); }
    if (d1 >= 0) { int p = atomicAdd(&d_cur[d1], 1); d_epk[p] = make_int2(s1, __float_as_int(w1)); }
    if (d2 >= 0) { int p = atomicAdd(&d_cur[d2], 1); d_epk[p] = make_int2(s2, __float_as_int(w2)); }
    if (d3 >= 0) { int p = atomicAdd(&d_cur[d3], 1); d_epk[p] = make_int2(s3, __float_as_int(w3)); }
}

__device__ __forceinline__ float2 h2f(unsigned int bits) {
    __half2 h = *(__half2*)&bits;
    return __half22float2(h);
}

// -------- fused layer: aggregate(h) -> @W -> +b -> LN -> ReLU [-> pool] -----
// One warp per node. Edges loaded COALESCED 32 at a time (lane j takes edge
// beg+j), then shfl-broadcast: one L2 round-trip for edges, then up to 32
// independent gathers pipelined back-to-back. 4 rotating accumulator pairs.
__global__ void __launch_bounds__(256)
fused_layer_kernel(const unsigned int* __restrict__ hin,
                   const float* __restrict__ W,
                   const float* __restrict__ cB,
                   const float* __restrict__ lg,
                   const float* __restrict__ lb,
                   unsigned int* __restrict__ hout,
                   const int* __restrict__ batch,
                   int do_pool, int n) {
    __shared__ float Ws[HID * HID];
    __shared__ float sB[HID], sG[HID], sLb[HID];
    int t = threadIdx.x;
    for (int i = t; i < HID * HID; i += blockDim.x) Ws[i] = W[i];
    if (t < HID) { sB[t] = cB[t]; sG[t] = lg[t]; sLb[t] = lb[t]; }
    __syncthreads();

    int warp = t >> 5, lane = t & 31;
    int nwarp = blockDim.x >> 5;

    for (int node = blockIdx.x * nwarp + warp; node < n; node += gridDim.x * nwarp) {
        int beg = d_ptr[node], end = d_ptr[node + 1];
        float ax0 = 0.f, ay0 = 0.f, ax1 = 0.f, ay1 = 0.f;
        float ax2 = 0.f, ay2 = 0.f, ax3 = 0.f, ay3 = 0.f;

        for (int base = beg; base < end; base += 32) {
            int idx = base + lane;
            // coalesced 32-edge load (one 256B transaction per warp)
            int2 myp = (idx < end) ? d_epk[idx] : make_int2(0, 0);
            int cnt = end - base;                 // edges in this chunk (may be >32)
            if (cnt >= 32) {
#pragma unroll
                for (int j = 0; j < 32; j++) {
                    int   s = __shfl_sync(0xffffffffu, myp.x, j);
                    float w = __int_as_float(__shfl_sync(0xffffffffu, myp.y, j));
                    float2 v = h2f(__ldg(hin + (size_t)s * 32 + lane));
                    if ((j & 3) == 0) { ax0 += v.x * w; ay0 += v.y * w; }
                    else if ((j & 3) == 1) { ax1 += v.x * w; ay1 += v.y * w; }
                    else if ((j & 3) == 2) { ax2 += v.x * w; ay2 += v.y * w; }
                    else { ax3 += v.x * w; ay3 += v.y * w; }
                }
            } else {
#pragma unroll
                for (int j = 0; j < 32; j++) {
                    int   s = __shfl_sync(0xffffffffu, myp.x, j);
                    float w = __int_as_float(__shfl_sync(0xffffffffu, myp.y, j));
                    if (j < cnt) {
                        float2 v = h2f(__ldg(hin + (size_t)s * 32 + lane));
                        if ((j & 3) == 0) { ax0 += v.x * w; ay0 += v.y * w; }
                        else if ((j & 3) == 1) { ax1 += v.x * w; ay1 += v.y * w; }
                        else if ((j & 3) == 2) { ax2 += v.x * w; ay2 += v.y * w; }
                        else { ax3 += v.x * w; ay3 += v.y * w; }
                    }
                }
            }
        }
        float ax = (ax0 + ax1) + (ax2 + ax3);
        float ay = (ay0 + ay1) + (ay2 + ay3);

        // in-warp GEMM: y = a @ W, a distributed 2 elems/lane
        float accx = 0.f, accy = 0.f;
#pragma unroll
        for (int k2 = 0; k2 < 32; k2++) {
            float hx = __shfl_sync(0xffffffffu, ax, k2);
            float hy = __shfl_sync(0xffffffffu, ay, k2);
            float2 w0 = ((const float2*)(Ws + (2 * k2) * HID))[lane];
            float2 w1 = ((const float2*)(Ws + (2 * k2 + 1) * HID))[lane];
            accx += hx * w0.x; accy += hx * w0.y;
            accx += hy * w1.x; accy += hy * w1.y;
        }
        accx += sB[2 * lane];
        accy += sB[2 * lane + 1];

        // LayerNorm over 64 + ReLU
        float sum = accx + accy;
#pragma unroll
        for (int o = 16; o > 0; o >>= 1) sum += __shfl_xor_sync(0xffffffffu, sum, o);
        float mu = sum * (1.f / 64.f);
        float dx = accx - mu, dy = accy - mu;
        float v2 = dx * dx + dy * dy;
#pragma unroll
        for (int o = 16; o > 0; o >>= 1) v2 += __shfl_xor_sync(0xffffffffu, v2, o);
        float inv = rsqrtf(v2 * (1.f / 64.f) + EPSV);
        float rx = fmaxf(dx * inv * sG[2 * lane] + sLb[2 * lane], 0.f);
        float ry = fmaxf(dy * inv * sG[2 * lane + 1] + sLb[2 * lane + 1], 0.f);

        if (do_pool) {
            int b = batch[node];
            atomicAdd(&d_psum[b * HID + 2 * lane], rx);
            atomicAdd(&d_psum[b * HID + 2 * lane + 1], ry);
            atomicMax(&d_pmax[b * HID + 2 * lane], __float_as_int(rx));
            atomicMax(&d_pmax[b * HID + 2 * lane + 1], __float_as_int(ry));
            if (lane == 0) atomicAdd(&d_pcnt[b], 1);
        } else {
            __half2 hv = __floats2half2_rn(rx, ry);
            hout[(size_t)node * 32 + lane] = *(unsigned int*)&hv;
        }
    }
}

// -------- final MLP --------
__global__ void mlp_kernel(const float* __restrict__ W1, const float* __restrict__ b1,
                           const float* __restrict__ W2, const float* __restrict__ b2,
                           float* __restrict__ out) {
    __shared__ float g[2 * HID];
    __shared__ float hr[HID];
    int gi = blockIdx.x, j = threadIdx.x;
    int cnt = d_pcnt[gi];
    float c = fmaxf((float)cnt, 1.f);
    g[j] = d_psum[gi * HID + j] / c;
    g[HID + j] = (cnt > 0) ? __int_as_float(d_pmax[gi * HID + j]) : 0.f;
    __syncthreads();
    float acc = b1[j];
#pragma unroll
    for (int k = 0; k < 2 * HID; k++) acc += g[k] * W1[k * HID + j];
    acc = fmaxf(acc, 0.f);
    hr[j] = acc * W2[j];
    __syncthreads();
    if (j < 32) {
        float s = hr[j] + hr[j + 32];
#pragma unroll
        for (int o = 16; o > 0; o >>= 1) s += __shfl_xor_sync(0xffffffffu, s, o);
        if (j == 0) out[gi] = s + b2[0];
    }
}

extern "C" void kernel_launch(void* const* d_in, const int* in_sizes, int n_in,
                              void* d_out, int out_size) {
    const int*   edge_index = (const int*)d_in[1];
    const float* edge_w     = (const float*)d_in[2];
    const int*   batch      = (const int*)d_in[3];
    const float* emb        = (const float*)d_in[4];
    const float* convW      = (const float*)d_in[5];
    const float* convB      = (const float*)d_in[6];
    const float* lnG        = (const float*)d_in[7];
    const float* lnB        = (const float*)d_in[8];
    const float* W1         = (const float*)d_in[9];
    const float* b1         = (const float*)d_in[10];
    const float* W2         = (const float*)d_in[11];
    const float* b2         = (const float*)d_in[12];
    float* out = (float*)d_out;

    int ne = in_sizes[2];
    int n  = in_sizes[3];
    const int* src = edge_index;
    const int* dst = edge_index + ne;

    unsigned int *hA, *hB;
    cudaGetSymbolAddress((void**)&hA, d_hhA);
    cudaGetSymbolAddress((void**)&hB, d_hhB);

    zero_kernel<<<256, 256>>>();
    convert_kernel<<<(NN * 32 + 255) / 256, 256>>>(emb);
    int T = (ne + 3) / 4;
    count_kernel<<<(T + 255) / 256, 256>>>(dst, ne, T);
    scan_phase1<<<SCAN_NBLK, SCAN_BS>>>(n);
    scan_phase2<<<1, SCAN_BS>>>();
    scan_phase3<<<SCAN_NBLK, SCAN_BS>>>(n);
    scatter_kernel<<<(T + 255) / 256, 256>>>(src, dst, edge_w, ne, T);

    const int THREADS = 256;
    const int WARPS_PER_BLK = THREADS / 32;
    int blocks = (n + 4 * WARPS_PER_BLK - 1) / (4 * WARPS_PER_BLK);

    fused_layer_kernel<<<blocks, THREADS>>>(hA, convW + 0 * HID * HID,
                                            convB + 0 * HID, lnG + 0 * HID,
                                            lnB + 0 * HID, hB, batch, 0, n);
    fused_layer_kernel<<<blocks, THREADS>>>(hB, convW + 1 * HID * HID,
                                            convB + 1 * HID, lnG + 1 * HID,
                                            lnB + 1 * HID, hA, batch, 0, n);
    fused_layer_kernel<<<blocks, THREADS>>>(hA, convW + 2 * HID * HID,
                                            convB + 2 * HID, lnG + 2 * HID,
                                            lnB + 2 * HID, (unsigned int*)nullptr, batch, 1, n);

    mlp_kernel<<<NG, HID>>>(W1, b1, W2, b2, out);
}

// round 7
// speedup vs baseline: 1.3157x; 1.3157x over previous
#include <cuda_runtime.h>
#include <cuda_fp16.h>

#define NN   50000
#define NE   1250000
#define HID  64
#define NL   3
#define NG   64
#define EPSV 1e-5f
#define CAP  80          // max in-degree bucket capacity (Poisson(25): P(>80) ~ 1e-20)

// -------- device scratch (no runtime allocation allowed) --------
__device__ unsigned int d_hhA[NN * 32];     // half2 node features (128B/row)
__device__ unsigned int d_hhB[NN * 32];
__device__ int2  d_bkt[NN * CAP];           // per-dst edge buckets: (src, w-bits)
__device__ int   d_cnt[NN];                 // per-dst degree counters
__device__ float d_psum[NG * HID];
__device__ int   d_pmax[NG * HID];          // float bits; post-ReLU values >= 0
__device__ int   d_pcnt[NG];

// -------- prep: zero counters/pools + convert emb fp32 -> half2 --------
__global__ void prep_kernel(const float* __restrict__ emb) {
    int i = blockIdx.x * blockDim.x + threadIdx.x;
    int stride = gridDim.x * blockDim.x;
    for (int k = i; k < NN * 32; k += stride) {
        float2 v = ((const float2*)emb)[k];
        __half2 h = __floats2half2_rn(v.x, v.y);
        d_hhA[k] = *(unsigned int*)&h;
    }
    for (int k = i; k < NN; k += stride) d_cnt[k] = 0;
    for (int k = i; k < NG * HID; k += stride) { d_psum[k] = 0.f; d_pmax[k] = 0; }
    if (i < NG) d_pcnt[i] = 0;
}

// -------- bucket scatter: count + place edges in one pass (4-way MLP) ------
__global__ void scatter_kernel(const int* __restrict__ src, const int* __restrict__ dst,
                               const float* __restrict__ w, int ne, int T) {
    int t = blockIdx.x * blockDim.x + threadIdx.x;
    if (t >= T) return;
    int e0 = t, e1 = t + T, e2 = t + 2 * T, e3 = t + 3 * T;
    int d0 = (e0 < ne) ? dst[e0] : -1;
    int d1 = (e1 < ne) ? dst[e1] : -1;
    int d2 = (e2 < ne) ? dst[e2] : -1;
    int d3 = (e3 < ne) ? dst[e3] : -1;
    int s0 = (e0 < ne) ? src[e0] : 0;
    int s1 = (e1 < ne) ? src[e1] : 0;
    int s2 = (e2 < ne) ? src[e2] : 0;
    int s3 = (e3 < ne) ? src[e3] : 0;
    float w0 = (e0 < ne) ? w[e0] : 0.f;
    float w1 = (e1 < ne) ? w[e1] : 0.f;
    float w2 = (e2 < ne) ? w[e2] : 0.f;
    float w3 = (e3 < ne) ? w[e3] : 0.f;
    if (d0 >= 0) { int p = atomicAdd(&d_cnt[d0], 1); if (p < CAP) d_bkt[d0 * CAP + p] = make_int2(s0, __float_as_int(w0)); }
    if (d1 >= 0) { int p = atomicAdd(&d_cnt[d1], 1); if (p < CAP) d_bkt[d1 * CAP + p] = make_int2(s1, __float_as_int(w1)); }
    if (d2 >= 0) { int p = atomicAdd(&d_cnt[d2], 1); if (p < CAP) d_bkt[d2 * CAP + p] = make_int2(s2, __float_as_int(w2)); }
    if (d3 >= 0) { int p = atomicAdd(&d_cnt[d3], 1); if (p < CAP) d_bkt[d3 * CAP + p] = make_int2(s3, __float_as_int(w3)); }
}

__device__ __forceinline__ float2 h2f(unsigned int bits) {
    __half2 h = *(__half2*)&bits;
    return __half22float2(h);
}

// -------- fused layer: aggregate(h) -> @W -> +b -> LN -> ReLU [-> pool] -----
// One warp per node; grid-stride; R5-style unroll-8 uniform edge loads
// (sequential per warp -> L1-resident), 8 independent gathers in flight.
__global__ void __launch_bounds__(256)
fused_layer_kernel(const unsigned int* __restrict__ hin,
                   const float* __restrict__ W,
                   const float* __restrict__ cB,
                   const float* __restrict__ lg,
                   const float* __restrict__ lb,
                   unsigned int* __restrict__ hout,
                   const int* __restrict__ batch,
                   int do_pool, int n) {
    __shared__ float Ws[HID * HID];
    __shared__ float sB[HID], sG[HID], sLb[HID];
    int t = threadIdx.x;
    for (int i = t; i < HID * HID; i += blockDim.x) Ws[i] = W[i];
    if (t < HID) { sB[t] = cB[t]; sG[t] = lg[t]; sLb[t] = lb[t]; }
    __syncthreads();

    int warp = t >> 5, lane = t & 31;
    int nwarp = blockDim.x >> 5;

    for (int node = blockIdx.x * nwarp + warp; node < n; node += gridDim.x * nwarp) {
        int cnt = min(d_cnt[node], CAP);
        const int2* eb = d_bkt + (size_t)node * CAP;
        float ax = 0.f, ay = 0.f;
        int e = 0;
        for (; e + 8 <= cnt; e += 8) {
            int2 p0 = eb[e + 0];
            int2 p1 = eb[e + 1];
            int2 p2 = eb[e + 2];
            int2 p3 = eb[e + 3];
            int2 p4 = eb[e + 4];
            int2 p5 = eb[e + 5];
            int2 p6 = eb[e + 6];
            int2 p7 = eb[e + 7];
            unsigned int g0 = __ldg(hin + (size_t)p0.x * 32 + lane);
            unsigned int g1 = __ldg(hin + (size_t)p1.x * 32 + lane);
            unsigned int g2 = __ldg(hin + (size_t)p2.x * 32 + lane);
            unsigned int g3 = __ldg(hin + (size_t)p3.x * 32 + lane);
            unsigned int g4 = __ldg(hin + (size_t)p4.x * 32 + lane);
            unsigned int g5 = __ldg(hin + (size_t)p5.x * 32 + lane);
            unsigned int g6 = __ldg(hin + (size_t)p6.x * 32 + lane);
            unsigned int g7 = __ldg(hin + (size_t)p7.x * 32 + lane);
            float2 v;
            v = h2f(g0); ax += v.x * __int_as_float(p0.y); ay += v.y * __int_as_float(p0.y);
            v = h2f(g1); ax += v.x * __int_as_float(p1.y); ay += v.y * __int_as_float(p1.y);
            v = h2f(g2); ax += v.x * __int_as_float(p2.y); ay += v.y * __int_as_float(p2.y);
            v = h2f(g3); ax += v.x * __int_as_float(p3.y); ay += v.y * __int_as_float(p3.y);
            v = h2f(g4); ax += v.x * __int_as_float(p4.y); ay += v.y * __int_as_float(p4.y);
            v = h2f(g5); ax += v.x * __int_as_float(p5.y); ay += v.y * __int_as_float(p5.y);
            v = h2f(g6); ax += v.x * __int_as_float(p6.y); ay += v.y * __int_as_float(p6.y);
            v = h2f(g7); ax += v.x * __int_as_float(p7.y); ay += v.y * __int_as_float(p7.y);
        }
        for (; e < cnt; e++) {
            int2 p = eb[e];
            unsigned int g = __ldg(hin + (size_t)p.x * 32 + lane);
            float2 v = h2f(g);
            float w = __int_as_float(p.y);
            ax += v.x * w; ay += v.y * w;
        }

        // in-warp GEMM: y = a @ W, a distributed 2 elems/lane
        float accx = 0.f, accy = 0.f;
#pragma unroll
        for (int k2 = 0; k2 < 32; k2++) {
            float hx = __shfl_sync(0xffffffffu, ax, k2);
            float hy = __shfl_sync(0xffffffffu, ay, k2);
            float2 w0 = ((const float2*)(Ws + (2 * k2) * HID))[lane];
            float2 w1 = ((const float2*)(Ws + (2 * k2 + 1) * HID))[lane];
            accx += hx * w0.x; accy += hx * w0.y;
            accx += hy * w1.x; accy += hy * w1.y;
        }
        accx += sB[2 * lane];
        accy += sB[2 * lane + 1];

        // LayerNorm over 64 + ReLU
        float sum = accx + accy;
#pragma unroll
        for (int o = 16; o > 0; o >>= 1) sum += __shfl_xor_sync(0xffffffffu, sum, o);
        float mu = sum * (1.f / 64.f);
        float dx = accx - mu, dy = accy - mu;
        float v2 = dx * dx + dy * dy;
#pragma unroll
        for (int o = 16; o > 0; o >>= 1) v2 += __shfl_xor_sync(0xffffffffu, v2, o);
        float inv = rsqrtf(v2 * (1.f / 64.f) + EPSV);
        float rx = fmaxf(dx * inv * sG[2 * lane] + sLb[2 * lane], 0.f);
        float ry = fmaxf(dy * inv * sG[2 * lane + 1] + sLb[2 * lane + 1], 0.f);

        if (do_pool) {
            int b = batch[node];
            atomicAdd(&d_psum[b * HID + 2 * lane], rx);
            atomicAdd(&d_psum[b * HID + 2 * lane + 1], ry);
            atomicMax(&d_pmax[b * HID + 2 * lane], __float_as_int(rx));
            atomicMax(&d_pmax[b * HID + 2 * lane + 1], __float_as_int(ry));
            if (lane == 0) atomicAdd(&d_pcnt[b], 1);
        } else {
            __half2 hv = __floats2half2_rn(rx, ry);
            hout[(size_t)node * 32 + lane] = *(unsigned int*)&hv;
        }
    }
}

// -------- final MLP --------
__global__ void mlp_kernel(const float* __restrict__ W1, const float* __restrict__ b1,
                           const float* __restrict__ W2, const float* __restrict__ b2,
                           float* __restrict__ out) {
    __shared__ float g[2 * HID];
    __shared__ float hr[HID];
    int gi = blockIdx.x, j = threadIdx.x;
    int cnt = d_pcnt[gi];
    float c = fmaxf((float)cnt, 1.f);
    g[j] = d_psum[gi * HID + j] / c;
    g[HID + j] = (cnt > 0) ? __int_as_float(d_pmax[gi * HID + j]) : 0.f;
    __syncthreads();
    float acc = b1[j];
#pragma unroll
    for (int k = 0; k < 2 * HID; k++) acc += g[k] * W1[k * HID + j];
    acc = fmaxf(acc, 0.f);
    hr[j] = acc * W2[j];
    __syncthreads();
    if (j < 32) {
        float s = hr[j] + hr[j + 32];
#pragma unroll
        for (int o = 16; o > 0; o >>= 1) s += __shfl_xor_sync(0xffffffffu, s, o);
        if (j == 0) out[gi] = s + b2[0];
    }
}

extern "C" void kernel_launch(void* const* d_in, const int* in_sizes, int n_in,
                              void* d_out, int out_size) {
    const int*   edge_index = (const int*)d_in[1];
    const float* edge_w     = (const float*)d_in[2];
    const int*   batch      = (const int*)d_in[3];
    const float* emb        = (const float*)d_in[4];
    const float* convW      = (const float*)d_in[5];
    const float* convB      = (const float*)d_in[6];
    const float* lnG        = (const float*)d_in[7];
    const float* lnB        = (const float*)d_in[8];
    const float* W1         = (const float*)d_in[9];
    const float* b1         = (const float*)d_in[10];
    const float* W2         = (const float*)d_in[11];
    const float* b2         = (const float*)d_in[12];
    float* out = (float*)d_out;

    int ne = in_sizes[2];
    int n  = in_sizes[3];
    const int* src = edge_index;
    const int* dst = edge_index + ne;

    unsigned int *hA, *hB;
    cudaGetSymbolAddress((void**)&hA, d_hhA);
    cudaGetSymbolAddress((void**)&hB, d_hhB);

    prep_kernel<<<1184, 256>>>(emb);                       // zero + convert, full-chip
    int T = (ne + 3) / 4;
    scatter_kernel<<<(T + 255) / 256, 256>>>(src, dst, edge_w, ne, T);

    const int THREADS = 256;
    const int WARPS_PER_BLK = THREADS / 32;
    int blocks = (n + 4 * WARPS_PER_BLK - 1) / (4 * WARPS_PER_BLK);

    fused_layer_kernel<<<blocks, THREADS>>>(hA, convW + 0 * HID * HID,
                                            convB + 0 * HID, lnG + 0 * HID,
                                            lnB + 0 * HID, hB, batch, 0, n);
    fused_layer_kernel<<<blocks, THREADS>>>(hB, convW + 1 * HID * HID,
                                            convB + 1 * HID, lnG + 1 * HID,
                                            lnB + 1 * HID, hA, batch, 0, n);
    fused_layer_kernel<<<blocks, THREADS>>>(hA, convW + 2 * HID * HID,
                                            convB + 2 * HID, lnG + 2 * HID,
                                            lnB + 2 * HID, (unsigned int*)nullptr, batch, 1, n);

    mlp_kernel<<<NG, HID>>>(W1, b1, W2, b2, out);
}

// round 8
// speedup vs baseline: 1.3498x; 1.0259x over previous
#include <cuda_runtime.h>
#include <cuda_fp16.h>

#define NN   50000
#define NE   1250000
#define HID  64
#define NL   3
#define NG   64
#define EPSV 1e-5f
#define CAP  80          // max in-degree bucket capacity (Poisson(25): P(>80) ~ 1e-20)
#define GR   128         // gemm rows per block tile

// -------- device scratch (no runtime allocation allowed) --------
__device__ unsigned int d_hhA[NN * 32];     // half2 node features (128B/row)
__device__ unsigned int d_hhB[NN * 32];
__device__ unsigned int d_hhM[NN * 32];     // m = h @ W (half2)
__device__ int2  d_bkt[NN * CAP];           // per-dst edge buckets: (src, w-bits)
__device__ int   d_cnt[NN];                 // per-dst degree counters
__device__ float d_psum[NG * HID];
__device__ int   d_pmax[NG * HID];          // float bits; post-ReLU values >= 0
__device__ int   d_pcnt[NG];

// -------- prep: zero counters/pools + convert emb fp32 -> half2 --------
__global__ void prep_kernel(const float* __restrict__ emb) {
    int i = blockIdx.x * blockDim.x + threadIdx.x;
    int stride = gridDim.x * blockDim.x;
    for (int k = i; k < NN * 32; k += stride) {
        float2 v = ((const float2*)emb)[k];
        __half2 h = __floats2half2_rn(v.x, v.y);
        d_hhA[k] = *(unsigned int*)&h;
    }
    for (int k = i; k < NN; k += stride) d_cnt[k] = 0;
    for (int k = i; k < NG * HID; k += stride) { d_psum[k] = 0.f; d_pmax[k] = 0; }
    if (i < NG) d_pcnt[i] = 0;
}

// -------- bucket scatter: count + place edges in one pass (4-way MLP) ------
__global__ void scatter_kernel(const int* __restrict__ src, const int* __restrict__ dst,
                               const float* __restrict__ w, int ne, int T) {
    int t = blockIdx.x * blockDim.x + threadIdx.x;
    if (t >= T) return;
    int e0 = t, e1 = t + T, e2 = t + 2 * T, e3 = t + 3 * T;
    int d0 = (e0 < ne) ? dst[e0] : -1;
    int d1 = (e1 < ne) ? dst[e1] : -1;
    int d2 = (e2 < ne) ? dst[e2] : -1;
    int d3 = (e3 < ne) ? dst[e3] : -1;
    int s0 = (e0 < ne) ? src[e0] : 0;
    int s1 = (e1 < ne) ? src[e1] : 0;
    int s2 = (e2 < ne) ? src[e2] : 0;
    int s3 = (e3 < ne) ? src[e3] : 0;
    float w0 = (e0 < ne) ? w[e0] : 0.f;
    float w1 = (e1 < ne) ? w[e1] : 0.f;
    float w2 = (e2 < ne) ? w[e2] : 0.f;
    float w3 = (e3 < ne) ? w[e3] : 0.f;
    if (d0 >= 0) { int p = atomicAdd(&d_cnt[d0], 1); if (p < CAP) d_bkt[d0 * CAP + p] = make_int2(s0, __float_as_int(w0)); }
    if (d1 >= 0) { int p = atomicAdd(&d_cnt[d1], 1); if (p < CAP) d_bkt[d1 * CAP + p] = make_int2(s1, __float_as_int(w1)); }
    if (d2 >= 0) { int p = atomicAdd(&d_cnt[d2], 1); if (p < CAP) d_bkt[d2 * CAP + p] = make_int2(s2, __float_as_int(w2)); }
    if (d3 >= 0) { int p = atomicAdd(&d_cnt[d3], 1); if (p < CAP) d_bkt[d3 * CAP + p] = make_int2(s3, __float_as_int(w3)); }
}

__device__ __forceinline__ float2 h2f(unsigned int bits) {
    __half2 h = *(__half2*)&bits;
    return __half22float2(h);
}

// -------- dense GEMM: m(fp16) = h(fp16) @ W(fp32) -------------------------
// 128-row x 64-col tile, 256 threads, 4x8 register tile per thread.
__global__ void __launch_bounds__(256)
gemm_kernel(const unsigned int* __restrict__ hin, const float* __restrict__ W,
            unsigned int* __restrict__ mout, int n) {
    __shared__ float Ws[HID * HID];                 // 16 KB
    __shared__ __half hs[GR][HID + 2];              // pad 2 halves -> conflict-free
    int t = threadIdx.x;
    for (int i = t; i < HID * HID; i += 256) Ws[i] = W[i];
    int row0 = blockIdx.x * GR;
    for (int i = t; i < GR * 32; i += 256) {
        int r = i >> 5, c = i & 31;
        unsigned int bits = 0;
        int gr = row0 + r;
        if (gr < n) bits = hin[(size_t)gr * 32 + c];
        *(unsigned int*)&hs[r][c * 2] = bits;
    }
    __syncthreads();

    int tx = t & 7;        // col group: cols tx*8 .. tx*8+7
    int ty = t >> 3;       // 0..31 -> rows ty, ty+32, ty+64, ty+96
    float acc[4][8];
#pragma unroll
    for (int r = 0; r < 4; r++)
#pragma unroll
        for (int j = 0; j < 8; j++) acc[r][j] = 0.f;

#pragma unroll 8
    for (int k = 0; k < HID; k++) {
        float4 wa = *(const float4*)&Ws[k * HID + tx * 8];
        float4 wb = *(const float4*)&Ws[k * HID + tx * 8 + 4];
        float hv[4];
        hv[0] = __half2float(hs[ty][k]);
        hv[1] = __half2float(hs[ty + 32][k]);
        hv[2] = __half2float(hs[ty + 64][k]);
        hv[3] = __half2float(hs[ty + 96][k]);
#pragma unroll
        for (int r = 0; r < 4; r++) {
            acc[r][0] += hv[r] * wa.x;
            acc[r][1] += hv[r] * wa.y;
            acc[r][2] += hv[r] * wa.z;
            acc[r][3] += hv[r] * wa.w;
            acc[r][4] += hv[r] * wb.x;
            acc[r][5] += hv[r] * wb.y;
            acc[r][6] += hv[r] * wb.z;
            acc[r][7] += hv[r] * wb.w;
        }
    }

#pragma unroll
    for (int r = 0; r < 4; r++) {
        int gr = row0 + ty + r * 32;
        if (gr < n) {
#pragma unroll
            for (int j = 0; j < 4; j++) {
                __half2 hv = __floats2half2_rn(acc[r][2 * j], acc[r][2 * j + 1]);
                mout[(size_t)gr * 32 + tx * 4 + j] = *(unsigned int*)&hv;
            }
        }
    }
}

// -------- aggregate(m) -> +b -> LN -> ReLU [-> pool] ----------------------
// One warp per node; grid-stride; unroll-8 uniform edge loads + 8 gathers.
__global__ void __launch_bounds__(256)
agg_kernel(const unsigned int* __restrict__ m,
           const float* __restrict__ cB,
           const float* __restrict__ lg,
           const float* __restrict__ lb,
           unsigned int* __restrict__ hout,
           const int* __restrict__ batch,
           int do_pool, int n) {
    __shared__ float sB[HID], sG[HID], sLb[HID];
    int t = threadIdx.x;
    if (t < HID) { sB[t] = cB[t]; sG[t] = lg[t]; sLb[t] = lb[t]; }
    __syncthreads();

    int warp = t >> 5, lane = t & 31;
    int nwarp = blockDim.x >> 5;

    for (int node = blockIdx.x * nwarp + warp; node < n; node += gridDim.x * nwarp) {
        int cnt = min(d_cnt[node], CAP);
        const int2* eb = d_bkt + (size_t)node * CAP;
        float ax = 0.f, ay = 0.f;
        int e = 0;
        for (; e + 8 <= cnt; e += 8) {
            int2 p0 = eb[e + 0];
            int2 p1 = eb[e + 1];
            int2 p2 = eb[e + 2];
            int2 p3 = eb[e + 3];
            int2 p4 = eb[e + 4];
            int2 p5 = eb[e + 5];
            int2 p6 = eb[e + 6];
            int2 p7 = eb[e + 7];
            unsigned int g0 = __ldg(m + (size_t)p0.x * 32 + lane);
            unsigned int g1 = __ldg(m + (size_t)p1.x * 32 + lane);
            unsigned int g2 = __ldg(m + (size_t)p2.x * 32 + lane);
            unsigned int g3 = __ldg(m + (size_t)p3.x * 32 + lane);
            unsigned int g4 = __ldg(m + (size_t)p4.x * 32 + lane);
            unsigned int g5 = __ldg(m + (size_t)p5.x * 32 + lane);
            unsigned int g6 = __ldg(m + (size_t)p6.x * 32 + lane);
            unsigned int g7 = __ldg(m + (size_t)p7.x * 32 + lane);
            float2 v;
            v = h2f(g0); ax += v.x * __int_as_float(p0.y); ay += v.y * __int_as_float(p0.y);
            v = h2f(g1); ax += v.x * __int_as_float(p1.y); ay += v.y * __int_as_float(p1.y);
            v = h2f(g2); ax += v.x * __int_as_float(p2.y); ay += v.y * __int_as_float(p2.y);
            v = h2f(g3); ax += v.x * __int_as_float(p3.y); ay += v.y * __int_as_float(p3.y);
            v = h2f(g4); ax += v.x * __int_as_float(p4.y); ay += v.y * __int_as_float(p4.y);
            v = h2f(g5); ax += v.x * __int_as_float(p5.y); ay += v.y * __int_as_float(p5.y);
            v = h2f(g6); ax += v.x * __int_as_float(p6.y); ay += v.y * __int_as_float(p6.y);
            v = h2f(g7); ax += v.x * __int_as_float(p7.y); ay += v.y * __int_as_float(p7.y);
        }
        for (; e < cnt; e++) {
            int2 p = eb[e];
            float2 v = h2f(__ldg(m + (size_t)p.x * 32 + lane));
            float w = __int_as_float(p.y);
            ax += v.x * w; ay += v.y * w;
        }

        float accx = ax + sB[2 * lane];
        float accy = ay + sB[2 * lane + 1];

        // LayerNorm over 64 + ReLU
        float sum = accx + accy;
#pragma unroll
        for (int o = 16; o > 0; o >>= 1) sum += __shfl_xor_sync(0xffffffffu, sum, o);
        float mu = sum * (1.f / 64.f);
        float dx = accx - mu, dy = accy - mu;
        float v2 = dx * dx + dy * dy;
#pragma unroll
        for (int o = 16; o > 0; o >>= 1) v2 += __shfl_xor_sync(0xffffffffu, v2, o);
        float inv = rsqrtf(v2 * (1.f / 64.f) + EPSV);
        float rx = fmaxf(dx * inv * sG[2 * lane] + sLb[2 * lane], 0.f);
        float ry = fmaxf(dy * inv * sG[2 * lane + 1] + sLb[2 * lane + 1], 0.f);

        if (do_pool) {
            int b = batch[node];
            atomicAdd(&d_psum[b * HID + 2 * lane], rx);
            atomicAdd(&d_psum[b * HID + 2 * lane + 1], ry);
            atomicMax(&d_pmax[b * HID + 2 * lane], __float_as_int(rx));
            atomicMax(&d_pmax[b * HID + 2 * lane + 1], __float_as_int(ry));
            if (lane == 0) atomicAdd(&d_pcnt[b], 1);
        } else {
            __half2 hv = __floats2half2_rn(rx, ry);
            hout[(size_t)node * 32 + lane] = *(unsigned int*)&hv;
        }
    }
}

// -------- final MLP --------
__global__ void mlp_kernel(const float* __restrict__ W1, const float* __restrict__ b1,
                           const float* __restrict__ W2, const float* __restrict__ b2,
                           float* __restrict__ out) {
    __shared__ float g[2 * HID];
    __shared__ float hr[HID];
    int gi = blockIdx.x, j = threadIdx.x;
    int cnt = d_pcnt[gi];
    float c = fmaxf((float)cnt, 1.f);
    g[j] = d_psum[gi * HID + j] / c;
    g[HID + j] = (cnt > 0) ? __int_as_float(d_pmax[gi * HID + j]) : 0.f;
    __syncthreads();
    float acc = b1[j];
#pragma unroll
    for (int k = 0; k < 2 * HID; k++) acc += g[k] * W1[k * HID + j];
    acc = fmaxf(acc, 0.f);
    hr[j] = acc * W2[j];
    __syncthreads();
    if (j < 32) {
        float s = hr[j] + hr[j + 32];
#pragma unroll
        for (int o = 16; o > 0; o >>= 1) s += __shfl_xor_sync(0xffffffffu, s, o);
        if (j == 0) out[gi] = s + b2[0];
    }
}

extern "C" void kernel_launch(void* const* d_in, const int* in_sizes, int n_in,
                              void* d_out, int out_size) {
    const int*   edge_index = (const int*)d_in[1];
    const float* edge_w     = (const float*)d_in[2];
    const int*   batch      = (const int*)d_in[3];
    const float* emb        = (const float*)d_in[4];
    const float* convW      = (const float*)d_in[5];
    const float* convB      = (const float*)d_in[6];
    const float* lnG        = (const float*)d_in[7];
    const float* lnB        = (const float*)d_in[8];
    const float* W1         = (const float*)d_in[9];
    const float* b1         = (const float*)d_in[10];
    const float* W2         = (const float*)d_in[11];
    const float* b2         = (const float*)d_in[12];
    float* out = (float*)d_out;

    int ne = in_sizes[2];
    int n  = in_sizes[3];
    const int* src = edge_index;
    const int* dst = edge_index + ne;

    unsigned int *hA, *hB, *hM;
    cudaGetSymbolAddress((void**)&hA, d_hhA);
    cudaGetSymbolAddress((void**)&hB, d_hhB);
    cudaGetSymbolAddress((void**)&hM, d_hhM);

    prep_kernel<<<1184, 256>>>(emb);
    int T = (ne + 3) / 4;
    scatter_kernel<<<(T + 255) / 256, 256>>>(src, dst, edge_w, ne, T);

    const int THREADS = 256;
    const int WARPS_PER_BLK = THREADS / 32;
    int agg_blocks = (n + 4 * WARPS_PER_BLK - 1) / (4 * WARPS_PER_BLK);
    int gemm_blocks = (n + GR - 1) / GR;

    // L0: hA -> m -> hB ; L1: hB -> m -> hA ; L2: hA -> m -> pool
    gemm_kernel<<<gemm_blocks, THREADS>>>(hA, convW + 0 * HID * HID, hM, n);
    agg_kernel<<<agg_blocks, THREADS>>>(hM, convB + 0 * HID, lnG + 0 * HID,
                                        lnB + 0 * HID, hB, batch, 0, n);
    gemm_kernel<<<gemm_blocks, THREADS>>>(hB, convW + 1 * HID * HID, hM, n);
    agg_kernel<<<agg_blocks, THREADS>>>(hM, convB + 1 * HID, lnG + 1 * HID,
                                        lnB + 1 * HID, hA, batch, 0, n);
    gemm_kernel<<<gemm_blocks, THREADS>>>(hA, convW + 2 * HID * HID, hM, n);
    agg_kernel<<<agg_blocks, THREADS>>>(hM, convB + 2 * HID, lnG + 2 * HID,
                                        lnB + 2 * HID, (unsigned int*)nullptr, batch, 1, n);

    mlp_kernel<<<NG, HID>>>(W1, b1, W2, b2, out);
}